// round 5
// baseline (speedup 1.0000x reference)
#include <cuda_runtime.h>
#include <cuda_bf16.h>
#include <cstdint>
#include <cstddef>

#define N_NODES 40000
#define N_EDGES 640000
#define IN_F    256
#define EDGE_F  64
#define OUT_F   128
#define NH      8
#define DH      16

// ---------------- scratch ----------------
__device__ __align__(16) float g_Wh[(size_t)N_NODES * OUT_F];
__device__ __align__(16) float g_ssrc[N_NODES * NH];
__device__ __align__(16) float g_sdst[N_NODES * NH];
__device__ __align__(16) float g_sval[(size_t)N_EDGES * NH];   // CSR-ordered edge scores
__device__ __align__(16) int   g_ssidx[N_EDGES];               // CSR-ordered src ids
__device__ __align__(16) int   g_count[N_NODES];
__device__ __align__(16) int   g_rowstart[N_NODES + 1];
__device__ __align__(16) int   g_cursor[N_NODES];
__device__ float g_weff[NH * EDGE_F];
__device__ float g_beff[NH];

// ---------------- helpers ----------------
__device__ __forceinline__ uint32_t smem_u32(const void* p) {
    uint32_t a;
    asm("{ .reg .u64 t; cvta.to.shared.u64 t, %1; cvt.u32.u64 %0, t; }" : "=r"(a) : "l"(p));
    return a;
}
__device__ __forceinline__ uint32_t swz(uint32_t off) {
    return off ^ ((off >> 3) & 0x70);
}
__device__ __forceinline__ void ldsm4(uint32_t& r0, uint32_t& r1, uint32_t& r2, uint32_t& r3, uint32_t addr) {
    asm volatile("ldmatrix.sync.aligned.m8n8.x4.shared.b16 {%0,%1,%2,%3}, [%4];"
                 : "=r"(r0), "=r"(r1), "=r"(r2), "=r"(r3) : "r"(addr));
}
__device__ __forceinline__ void mma16816(float* c, uint32_t a0, uint32_t a1, uint32_t a2, uint32_t a3,
                                         uint32_t b0, uint32_t b1) {
    asm volatile("mma.sync.aligned.m16n8k16.row.col.f32.bf16.bf16.f32 "
                 "{%0,%1,%2,%3}, {%4,%5,%6,%7}, {%8,%9}, {%0,%1,%2,%3};"
                 : "+f"(c[0]), "+f"(c[1]), "+f"(c[2]), "+f"(c[3])
                 : "r"(a0), "r"(a1), "r"(a2), "r"(a3), "r"(b0), "r"(b1));
}
__device__ __forceinline__ uint32_t pack_bf16x2(float a, float b) {
    __nv_bfloat16 x = __float2bfloat16(a), y = __float2bfloat16(b);
    return (uint32_t)__bfloat16_as_ushort(x) | ((uint32_t)__bfloat16_as_ushort(y) << 16);
}

// ---------------- K0: dst histogram + fold attn into edge_w ----------------
// (g_count must be zeroed beforehand via cudaMemsetAsync)
__global__ void k_init(const int* __restrict__ dst,
                       const float* __restrict__ edge_w,
                       const float* __restrict__ edge_b,
                       const float* __restrict__ attn) {
    int e = blockIdx.x * blockDim.x + threadIdx.x;
    if (e < N_EDGES) atomicAdd(&g_count[dst[e]], 1);
    if (blockIdx.x == 0) {
        for (int i = threadIdx.x; i < NH * EDGE_F; i += blockDim.x) {
            int h = i >> 6, k = i & 63;
            float s = 0.f;
            #pragma unroll
            for (int d = 0; d < DH; d++)
                s += edge_w[(h * DH + d) * EDGE_F + k] * attn[h * 48 + 32 + d];
            g_weff[i] = s;
        }
        if (threadIdx.x < NH) {
            int h = threadIdx.x;
            float s = 0.f;
            #pragma unroll
            for (int d = 0; d < DH; d++)
                s += edge_b[h * DH + d] * attn[h * 48 + 32 + d];
            g_beff[h] = s;
        }
    }
}

// ---------------- K1: bf16-split MMA GEMM: Wh = A @ B^T + bias, fused s_src/s_dst ----------------
#define SMEM_GEMM 65536
__global__ __launch_bounds__(256) void k_gemm(const float* __restrict__ A,
                                              const float* __restrict__ B,
                                              const float* __restrict__ bias,
                                              const float* __restrict__ attn) {
    extern __shared__ char sm[];
    const uint32_t A_HI = 0, A_LO = 16384, B_HI = 32768, B_LO = 49152;
    uint32_t sbase = smem_u32(sm);

    int tid = threadIdx.x, w = tid >> 5, lane = tid & 31;
    int m0 = blockIdx.x * 128;
    int wm = (w >> 1) * 32, wn = (w & 1) * 64;
    int g = lane >> 2, t = lane & 3;

    float c[2][8][4];
    #pragma unroll
    for (int mt = 0; mt < 2; mt++)
        #pragma unroll
        for (int nt = 0; nt < 8; nt++)
            #pragma unroll
            for (int j = 0; j < 4; j++) c[mt][nt][j] = 0.f;

    #pragma unroll 1
    for (int chunk = 0; chunk < 4; chunk++) {
        int k0 = chunk << 6;
        #pragma unroll
        for (int i = 0; i < 8; i++) {
            int idx = tid + i * 256;
            int r = idx >> 4;
            int cc = (idx & 15) << 2;
            int m = m0 + r;
            float4 va = (m < N_NODES) ? *(const float4*)&A[(size_t)m * IN_F + k0 + cc]
                                      : make_float4(0.f, 0.f, 0.f, 0.f);
            float4 vb = *(const float4*)&B[(size_t)r * IN_F + k0 + cc];
            uint32_t o = swz((uint32_t)(r * 128 + cc * 2));
            {
                float h0 = __bfloat162float(__float2bfloat16(va.x));
                float h1 = __bfloat162float(__float2bfloat16(va.y));
                float h2 = __bfloat162float(__float2bfloat16(va.z));
                float h3 = __bfloat162float(__float2bfloat16(va.w));
                *(uint2*)(sm + A_HI + o) = make_uint2(pack_bf16x2(h0, h1), pack_bf16x2(h2, h3));
                *(uint2*)(sm + A_LO + o) = make_uint2(pack_bf16x2(va.x - h0, va.y - h1),
                                                      pack_bf16x2(va.z - h2, va.w - h3));
            }
            {
                float h0 = __bfloat162float(__float2bfloat16(vb.x));
                float h1 = __bfloat162float(__float2bfloat16(vb.y));
                float h2 = __bfloat162float(__float2bfloat16(vb.z));
                float h3 = __bfloat162float(__float2bfloat16(vb.w));
                *(uint2*)(sm + B_HI + o) = make_uint2(pack_bf16x2(h0, h1), pack_bf16x2(h2, h3));
                *(uint2*)(sm + B_LO + o) = make_uint2(pack_bf16x2(vb.x - h0, vb.y - h1),
                                                      pack_bf16x2(vb.z - h2, vb.w - h3));
            }
        }
        __syncthreads();

        int lr = lane & 15, lc = (lane >> 4) << 3;
        #pragma unroll
        for (int ks = 0; ks < 4; ks++) {
            int kk = (ks << 4) + lc;
            uint32_t ao0 = swz((uint32_t)((wm + lr) * 128 + kk * 2));
            uint32_t ao1 = swz((uint32_t)((wm + 16 + lr) * 128 + kk * 2));
            uint32_t ah[2][4], al[2][4];
            ldsm4(ah[0][0], ah[0][1], ah[0][2], ah[0][3], sbase + A_HI + ao0);
            ldsm4(ah[1][0], ah[1][1], ah[1][2], ah[1][3], sbase + A_HI + ao1);
            ldsm4(al[0][0], al[0][1], al[0][2], al[0][3], sbase + A_LO + ao0);
            ldsm4(al[1][0], al[1][1], al[1][2], al[1][3], sbase + A_LO + ao1);
            #pragma unroll
            for (int np = 0; np < 4; np++) {
                uint32_t bo = swz((uint32_t)((wn + np * 16 + lr) * 128 + kk * 2));
                uint32_t bh[4], bl[4];
                ldsm4(bh[0], bh[1], bh[2], bh[3], sbase + B_HI + bo);
                ldsm4(bl[0], bl[1], bl[2], bl[3], sbase + B_LO + bo);
                #pragma unroll
                for (int mt = 0; mt < 2; mt++) {
                    mma16816(c[mt][np * 2],     ah[mt][0], ah[mt][1], ah[mt][2], ah[mt][3], bh[0], bh[2]);
                    mma16816(c[mt][np * 2],     ah[mt][0], ah[mt][1], ah[mt][2], ah[mt][3], bl[0], bl[2]);
                    mma16816(c[mt][np * 2],     al[mt][0], al[mt][1], al[mt][2], al[mt][3], bh[0], bh[2]);
                    mma16816(c[mt][np * 2 + 1], ah[mt][0], ah[mt][1], ah[mt][2], ah[mt][3], bh[1], bh[3]);
                    mma16816(c[mt][np * 2 + 1], ah[mt][0], ah[mt][1], ah[mt][2], ah[mt][3], bl[1], bl[3]);
                    mma16816(c[mt][np * 2 + 1], al[mt][0], al[mt][1], al[mt][2], al[mt][3], bh[1], bh[3]);
                }
            }
        }
        __syncthreads();
    }

    // ---- epilogue ----
    float as0[8], as1[8], ad0[8], ad1[8], bb0[8], bb1[8];
    #pragma unroll
    for (int nt = 0; nt < 8; nt++) {
        int col = wn + nt * 8 + t * 2;
        int h = col >> 4, d = col & 15;
        as0[nt] = attn[h * 48 + d];      as1[nt] = attn[h * 48 + d + 1];
        ad0[nt] = attn[h * 48 + 16 + d]; ad1[nt] = attn[h * 48 + 16 + d + 1];
        bb0[nt] = bias[col];             bb1[nt] = bias[col + 1];
    }
    float ps[2][2][4], pd[2][2][4];
    #pragma unroll
    for (int mt = 0; mt < 2; mt++)
        #pragma unroll
        for (int hf = 0; hf < 2; hf++)
            #pragma unroll
            for (int hh = 0; hh < 4; hh++) { ps[mt][hf][hh] = 0.f; pd[mt][hf][hh] = 0.f; }

    #pragma unroll
    for (int mt = 0; mt < 2; mt++) {
        #pragma unroll
        for (int hf = 0; hf < 2; hf++) {
            int m = m0 + wm + mt * 16 + g + hf * 8;
            bool ok = (m < N_NODES);
            #pragma unroll
            for (int nt = 0; nt < 8; nt++) {
                float v0 = c[mt][nt][hf * 2 + 0] + bb0[nt];
                float v1 = c[mt][nt][hf * 2 + 1] + bb1[nt];
                if (ok) {
                    int col = wn + nt * 8 + t * 2;
                    *(float2*)&g_Wh[(size_t)m * OUT_F + col] = make_float2(v0, v1);
                }
                ps[mt][hf][nt >> 1] += v0 * as0[nt] + v1 * as1[nt];
                pd[mt][hf][nt >> 1] += v0 * ad0[nt] + v1 * ad1[nt];
            }
        }
    }
    #pragma unroll
    for (int mt = 0; mt < 2; mt++)
        #pragma unroll
        for (int hf = 0; hf < 2; hf++)
            #pragma unroll
            for (int hh = 0; hh < 4; hh++) {
                float s = ps[mt][hf][hh], d2 = pd[mt][hf][hh];
                s += __shfl_xor_sync(0xffffffffu, s, 1);
                s += __shfl_xor_sync(0xffffffffu, s, 2);
                d2 += __shfl_xor_sync(0xffffffffu, d2, 1);
                d2 += __shfl_xor_sync(0xffffffffu, d2, 2);
                if (t == 0) {
                    int m = m0 + wm + mt * 16 + g + hf * 8;
                    if (m < N_NODES) {
                        int h = (w & 1) * 4 + hh;
                        g_ssrc[m * NH + h] = s;
                        g_sdst[m * NH + h] = d2;
                    }
                }
            }
}

// ---------------- K2: single-phase exclusive scan (1024 threads, 40 items each) ----------------
__global__ __launch_bounds__(1024) void k_scan() {
    __shared__ int wsum[32];
    int tid = threadIdx.x, lane = tid & 31, wid = tid >> 5;
    int base = tid * 40;
    int4 v[10];
    #pragma unroll
    for (int j = 0; j < 10; j++) {
        int o = base + j * 4;
        v[j] = (o < N_NODES) ? *(const int4*)&g_count[o] : make_int4(0, 0, 0, 0);
    }
    int t = 0;
    #pragma unroll
    for (int j = 0; j < 10; j++) t += v[j].x + v[j].y + v[j].z + v[j].w;
    int x = t;
    #pragma unroll
    for (int o = 1; o < 32; o <<= 1) {
        int y = __shfl_up_sync(0xffffffffu, x, o);
        if (lane >= o) x += y;
    }
    if (lane == 31) wsum[wid] = x;
    __syncthreads();
    if (wid == 0) {
        int wv = wsum[lane], xx = wv;
        #pragma unroll
        for (int o = 1; o < 32; o <<= 1) {
            int y = __shfl_up_sync(0xffffffffu, xx, o);
            if (lane >= o) xx += y;
        }
        wsum[lane] = xx - wv;
    }
    __syncthreads();
    int run = (x - t) + wsum[wid];
    #pragma unroll
    for (int j = 0; j < 10; j++) {
        int o = base + j * 4;
        int4 r;
        r.x = run; run += v[j].x;
        r.y = run; run += v[j].y;
        r.z = run; run += v[j].z;
        r.w = run; run += v[j].w;
        if (o < N_NODES) {
            *(int4*)&g_rowstart[o] = r;
            *(int4*)&g_cursor[o]   = r;
        }
    }
    if (tid == 1023) g_rowstart[N_NODES] = run;
}

// ---------------- K3: s_e + s_src fold + direct CSR scatter ----------------
__global__ __launch_bounds__(128) void k_se(const float* __restrict__ EF,
                                            const int* __restrict__ src,
                                            const int* __restrict__ dst) {
    __shared__ float xs[128 * 65];
    __shared__ float ws[NH * EDGE_F];
    __shared__ float bs[NH];
    int tid = threadIdx.x;
    for (int i = tid; i < NH * EDGE_F; i += 128) ws[i] = g_weff[i];
    if (tid < NH) bs[tid] = g_beff[tid];

    int ebase = blockIdx.x * 128;
    const float* p = EF + (size_t)ebase * EDGE_F;
    #pragma unroll
    for (int i = 0; i < 64; i++) {
        int idx = tid + i * 128;
        xs[(idx >> 6) * 65 + (idx & 63)] = p[idx];
    }
    __syncthreads();

    int e = ebase + tid;
    float acc[NH];
    #pragma unroll
    for (int h = 0; h < NH; h++) acc[h] = bs[h];
    const float* xr = &xs[tid * 65];
    #pragma unroll
    for (int gq = 0; gq < 16; gq++) {
        float x0 = xr[gq * 4], x1 = xr[gq * 4 + 1], x2 = xr[gq * 4 + 2], x3 = xr[gq * 4 + 3];
        #pragma unroll
        for (int h = 0; h < NH; h++) {
            float4 wv = *(const float4*)&ws[h * EDGE_F + gq * 4];
            acc[h] += x0 * wv.x + x1 * wv.y + x2 * wv.z + x3 * wv.w;
        }
    }
    int s = src[e], d = dst[e];
    int pos = atomicAdd(&g_cursor[d], 1);
    g_ssidx[pos] = s;
    float4 s0 = *(const float4*)&g_ssrc[s * NH];
    float4 s1 = *(const float4*)&g_ssrc[s * NH + 4];
    *(float4*)&g_sval[(size_t)pos * NH]     = make_float4(acc[0] + s0.x, acc[1] + s0.y, acc[2] + s0.z, acc[3] + s0.w);
    *(float4*)&g_sval[(size_t)pos * NH + 4] = make_float4(acc[4] + s1.x, acc[5] + s1.y, acc[6] + s1.z, acc[7] + s1.w);
}

// ---------------- K4: gather per node (warp/node), sequential CSR streams ----------------
__global__ __launch_bounds__(256) void k_gather(float* __restrict__ out) {
    int warp = (blockIdx.x * blockDim.x + threadIdx.x) >> 5;
    int lane = threadIdx.x & 31;
    if (warp >= N_NODES) return;
    int h = lane >> 2;
    float sd = g_sdst[warp * NH + h];
    int beg = g_rowstart[warp], end = g_rowstart[warp + 1];
    float4 acc = make_float4(0.f, 0.f, 0.f, 0.f);
    float z = 0.f;
    for (int i = beg; i < end; i++) {
        int s = g_ssidx[i];
        float sv = g_sval[(size_t)i * NH + h] + sd;
        sv = fmaxf(sv, 0.2f * sv);
        float ex = __expf(sv);
        z += ex;
        float4 wv = *(const float4*)&g_Wh[(size_t)s * OUT_F + lane * 4];
        acc.x += ex * wv.x; acc.y += ex * wv.y;
        acc.z += ex * wv.z; acc.w += ex * wv.w;
    }
    float4 o = make_float4(0.f, 0.f, 0.f, 0.f);
    if (end > beg) {
        float inv = 1.f / z;
        o = make_float4(acc.x * inv, acc.y * inv, acc.z * inv, acc.w * inv);
    }
    *(float4*)&out[(size_t)warp * OUT_F + lane * 4] = o;
}

// ---------------- launch ----------------
extern "C" void kernel_launch(void* const* d_in, const int* in_sizes, int n_in,
                              void* d_out, int out_size) {
    const float* node_feats = (const float*)d_in[0];
    const float* edge_feats = (const float*)d_in[1];
    const int*   src        = (const int*)d_in[2];
    const int*   dst        = (const int*)d_in[3];
    const float* node_w     = (const float*)d_in[4];
    const float* node_b     = (const float*)d_in[5];
    const float* edge_w     = (const float*)d_in[6];
    const float* edge_b     = (const float*)d_in[7];
    const float* attn       = (const float*)d_in[8];
    float* out = (float*)d_out;

    void* count_ptr = nullptr;
    cudaGetSymbolAddress(&count_ptr, g_count);
    cudaMemsetAsync(count_ptr, 0, N_NODES * sizeof(int));

    cudaFuncSetAttribute(k_gemm, cudaFuncAttributeMaxDynamicSharedMemorySize, SMEM_GEMM);

    k_init<<<(N_EDGES + 255) / 256, 256>>>(dst, edge_w, edge_b, attn);
    k_gemm<<<(N_NODES + 127) / 128, 256, SMEM_GEMM>>>(node_feats, node_w, node_b, attn);
    k_scan<<<1, 1024>>>();
    k_se<<<N_EDGES / 128, 128>>>(edge_feats, src, dst);
    k_gather<<<(N_NODES * 32 + 255) / 256, 256>>>(out);
}